// round 6
// baseline (speedup 1.0000x reference)
#include <cuda_runtime.h>
#include <math.h>

#define N_MAX   196608
#define TILE    96
#define TMAX    2048
#define MAXDET  100
#define MAXC    448           // max phase-1 candidates
#define WORDS   14            // MAXC / 32
#define SPAN    160u          // candidate window below max, ordered-ulp units
#define LOU     0xBC23D70Au   // ordf(0.01f)
#define NMS_T   512

__device__ float    g_scores[N_MAX];
__device__ unsigned g_maxu;   // zero-init; reset by nms each replay

__device__ __forceinline__ unsigned ordf(float f) {
    unsigned u = __float_as_uint(f);
    return (u & 0x80000000u) ? ~u : (u | 0x80000000u);
}
__device__ __forceinline__ float unordf(unsigned u) {
    return __uint_as_float((u & 0x80000000u) ? (u ^ 0x80000000u) : ~u);
}
__device__ __forceinline__ float read_dim(const void* p) {
    int iv = *(const int*)p;
    if (iv >= 1 && iv <= (1 << 20)) return (float)iv;
    float fv = *(const float*)p;
    if (fv >= 1.0f && fv <= 1048576.0f) return fv;
    double dv = *(const double*)p;
    if (dv >= 1.0 && dv <= 1048576.0) return (float)dv;
    long long lv = *(const long long*)p;
    return (float)lv;
}
__device__ __forceinline__ bool iou_gt_half(float4 A, float4 B) {
    float x1 = fmaxf(A.x, B.x), y1 = fmaxf(A.y, B.y);
    float x2 = fminf(A.z, B.z), y2 = fminf(A.w, B.w);
    float inter = fmaxf(x2 - x1, 0.0f) * fmaxf(y2 - y1, 0.0f);
    float a1 = (A.z - A.x) * (A.w - A.y);
    float a2 = (B.z - B.x) * (B.w - B.y);
    float iou = inter / (a1 + a2 - inter + 1e-8f);
    return iou > 0.5f;
}
__device__ __forceinline__ float4 make_box(float4 a, float4 r,
                                           float imh, float imw) {
    float wa  = a.z - a.x;
    float ha  = a.w - a.y;
    float cxa = a.x + 0.5f * wa;
    float cya = a.y + 0.5f * ha;
    float cx  = cxa + r.x * 0.1f * wa;
    float cy  = cya + r.y * 0.1f * ha;
    float w   = expf(r.z * 0.2f) * wa;
    float h   = expf(r.w * 0.2f) * ha;
    float4 b;
    b.x = fminf(fmaxf(cx - 0.5f * w, 0.0f), imw);
    b.y = fminf(fmaxf(cy - 0.5f * h, 0.0f), imh);
    b.z = fminf(fmaxf(cx + 0.5f * w, 0.0f), imw);
    b.w = fminf(fmaxf(cy + 0.5f * h, 0.0f), imh);
    return b;
}

// ---------------------------------------------------------------------------
// Kernel 1 (C==90): 8 threads per anchor-pair, 2 pairs per group for 12-deep
// MLP; register max + 3 shuffles; writes scores only. Zero smem atomics.
// ---------------------------------------------------------------------------
__global__ void decode90_kernel(const float* __restrict__ cls, int N) {
    const unsigned FULL = 0xffffffffu;
    int tid = threadIdx.x;
    int sub = tid & 7;
    int grp = tid >> 3;
    long long P0 = ((long long)blockIdx.x * 32 + grp) * 2;
    int pairs = N >> 1;

    unsigned mA0 = 0u, mB0 = 0u, mA1 = 0u, mB1 = 0u;
    #pragma unroll
    for (int pp = 0; pp < 2; pp++) {
        long long P = P0 + pp;
        unsigned* pA = pp ? &mA1 : &mA0;
        unsigned* pB = pp ? &mB1 : &mB0;
        if (P < pairs) {
            const float4* src = (const float4*)cls + P * 45;
            #pragma unroll
            for (int it = 0; it < 6; it++) {
                int q = sub + it * 8;
                if (q < 45) {
                    float4 v = src[q];
                    if (q < 22) {
                        *pA = max(*pA, ordf(fmaxf(fmaxf(v.x, v.y), fmaxf(v.z, v.w))));
                    } else if (q == 22) {   // floats 88..91: x,y -> A; z,w -> B
                        *pA = max(*pA, ordf(fmaxf(v.x, v.y)));
                        *pB = max(*pB, ordf(fmaxf(v.z, v.w)));
                    } else {
                        *pB = max(*pB, ordf(fmaxf(fmaxf(v.x, v.y), fmaxf(v.z, v.w))));
                    }
                }
            }
        }
    }
    #pragma unroll
    for (int off = 1; off <= 4; off <<= 1) {
        mA0 = max(mA0, __shfl_xor_sync(FULL, mA0, off));
        mB0 = max(mB0, __shfl_xor_sync(FULL, mB0, off));
        mA1 = max(mA1, __shfl_xor_sync(FULL, mA1, off));
        mB1 = max(mB1, __shfl_xor_sync(FULL, mB1, off));
    }
    if (P0 < pairs && sub < 2) {
        unsigned u = sub ? mB0 : mA0;
        float best = unordf(u);
        g_scores[2 * P0 + sub] = (best > 0.01f) ? best : -INFINITY;
    }
    if (P0 + 1 < pairs && sub < 2) {
        unsigned u = sub ? mB1 : mA1;
        float best = unordf(u);
        g_scores[2 * (P0 + 1) + sub] = (best > 0.01f) ? best : -INFINITY;
    }
    if ((N & 1) && blockIdx.x == 0 && tid == 0) {
        const float* row = cls + (long long)(N - 1) * 90;
        unsigned u = 0u;
        for (int j = 0; j < 90; j++) u = max(u, ordf(row[j]));
        float best = unordf(u);
        g_scores[N - 1] = (best > 0.01f) ? best : -INFINITY;
        atomicMax(&g_maxu, u);
    }
    unsigned wm = max(max(mA0, mB0), max(mA1, mB1));
    wm = max(wm, __shfl_xor_sync(FULL, wm, 8));
    wm = max(wm, __shfl_xor_sync(FULL, wm, 16));
    if ((tid & 31) == 0) atomicMax(&g_maxu, wm);
}

// Generic-C path: warp per anchor.
__global__ void decodegen_kernel(const float* __restrict__ cls, int N, int C) {
    const unsigned FULL = 0xffffffffu;
    int warp = (blockIdx.x * blockDim.x + threadIdx.x) >> 5;
    int lane = threadIdx.x & 31;
    if (warp >= N) return;
    const float* row = cls + (long long)warp * C;
    unsigned u = 0u;
    for (int j = lane; j < C; j += 32) u = max(u, ordf(row[j]));
    #pragma unroll
    for (int off = 16; off; off >>= 1)
        u = max(u, __shfl_xor_sync(FULL, u, off));
    if (lane == 0) {
        float best = unordf(u);
        g_scores[warp] = (best > 0.01f) ? best : -INFINITY;
        atomicMax(&g_maxu, u);
    }
}

// ---------------------------------------------------------------------------
// Kernel 2: single block. Collect window candidates, bitonic sort, lazy box
// decode, parallel suppression bitmatrix, greedy resolve (exact reference
// order), class argmax, output. Exact fallback for adversarial inputs.
// ---------------------------------------------------------------------------
__global__ void nms_kernel(float* __restrict__ out,
                           const float* __restrict__ cls,
                           const float* __restrict__ reg,
                           const float* __restrict__ anc,
                           const void* ph, const void* pw,
                           int N, int C) {
    // sBuf layout (phase 1): keys[512] | cbox[MAXC] | mat[MAXC*WORDS]
    // fallback reuses sBuf as tile-key array ull[TMAX] (phase-1 data dead).
    __shared__ __align__(16) unsigned char sBuf[4096 + MAXC * 16 + MAXC * WORDS * 4];
    unsigned long long* sKeys = (unsigned long long*)sBuf;
    float4*   sCBox = (float4*)(sBuf + 4096);
    unsigned* sMat  = (unsigned*)(sBuf + 4096 + MAXC * 16);
    unsigned long long* sTile = (unsigned long long*)sBuf;

    __shared__ unsigned sSup[WORDS];
    __shared__ int    sOrder[MAXDET];
    __shared__ float4 sSelBox[MAXDET];
    __shared__ int    sSelIdx[MAXDET];
    __shared__ float  sSelScore[MAXDET];
    __shared__ int    sCnt, sNsel, sSup1;
    __shared__ unsigned sMaxu;
    __shared__ float4 sBx;
    __shared__ unsigned long long sWarp[16];
    __shared__ unsigned long long sTileP[3];

    int tid  = threadIdx.x;
    int wid  = tid >> 5;
    int lane = tid & 31;
    const unsigned FULL = 0xffffffffu;

    float imw = read_dim(pw);
    float imh = read_dim(ph);

    if (tid == 0) {
        sCnt = 0; sNsel = 0;
        sMaxu = g_maxu;
        g_maxu = 0u;          // reset for next graph replay
    }
    if (tid < WORDS) sSup[tid] = 0u;
    __syncthreads();

    unsigned maxu = sMaxu;
    unsigned cutU = (maxu > LOU + 1u + SPAN) ? (maxu - SPAN) : (LOU + 1u);

    // ---- collect candidates from g_scores (float4 grid-stride) ----
    {
        int n4 = N >> 2;
        const float4* s4 = (const float4*)g_scores;
        for (int k = tid; k < n4; k += NMS_T) {
            float4 v = s4[k];
            float vv[4] = {v.x, v.y, v.z, v.w};
            #pragma unroll
            for (int c = 0; c < 4; c++) {
                unsigned u = ordf(vv[c]);
                if (u >= cutU) {
                    int pos = atomicAdd(&sCnt, 1);
                    if (pos < MAXC)
                        sKeys[pos] = ((unsigned long long)u << 32)
                                   | (unsigned)(~(4 * k + c));
                }
            }
        }
        for (int i = (n4 << 2) + tid; i < N; i += NMS_T) {
            unsigned u = ordf(g_scores[i]);
            if (u >= cutU) {
                int pos = atomicAdd(&sCnt, 1);
                if (pos < MAXC)
                    sKeys[pos] = ((unsigned long long)u << 32) | (unsigned)(~i);
            }
        }
    }
    __syncthreads();

    bool ovf = sCnt > MAXC;
    int  cnt = ovf ? 0 : sCnt;

    // ---- bitonic sort, descending ----
    int M = 2; while (M < cnt) M <<= 1;
    for (int k = tid + cnt; k < M; k += NMS_T) sKeys[k] = 0ull;
    __syncthreads();
    if (cnt > 1) {
        for (int k2 = 2; k2 <= M; k2 <<= 1) {
            for (int j = k2 >> 1; j > 0; j >>= 1) {
                for (int i = tid; i < M; i += NMS_T) {
                    int l = i ^ j;
                    if (l > i) {
                        unsigned long long a = sKeys[i], b = sKeys[l];
                        bool desc = ((i & k2) == 0);
                        if (desc ? (a < b) : (a > b)) { sKeys[i] = b; sKeys[l] = a; }
                    }
                }
                __syncthreads();
            }
        }
    }

    // ---- lazy decode candidate boxes ----
    if (tid < cnt) {
        unsigned long long key = sKeys[tid];
        int idx = (int)(~(unsigned)(key & 0xffffffffu));
        sCBox[tid] = make_box(((const float4*)anc)[idx],
                              ((const float4*)reg)[idx], imh, imw);
    }
    __syncthreads();

    // ---- parallel suppression bitmatrix ----
    int nW = (cnt + 31) >> 5;
    for (int r = tid; r < cnt; r += NMS_T) {
        float4 br = sCBox[r];
        for (int w = 0; w < nW; w++) {
            unsigned mm = 0;
            int base = w << 5;
            int lim  = min(32, cnt - base);
            for (int b = 0; b < lim; b++)
                mm |= ((unsigned)iou_gt_half(br, sCBox[base + b])) << b;
            sMat[r * WORDS + w] = mm;
        }
    }
    __syncthreads();

    // ---- greedy resolve in sorted order (warp 0) ----
    if (tid < 32) {
        int nsel = 0;
        for (int cb = 0; cb < cnt && nsel < MAXDET; cb += 32) {
            int cw = cb >> 5;
            bool valid = (cb + tid) < cnt;
            unsigned supW = sSup[cw];
            bool alive = valid && !((supW >> tid) & 1u);
            unsigned am = __ballot_sync(FULL, alive);
            unsigned selM = 0;
            while (am && nsel < MAXDET) {
                int l = __ffs(am) - 1;
                selM |= 1u << l;
                unsigned row = sMat[(cb + l) * WORDS + cw];
                if (tid == l) alive = false;
                else if (tid > l && ((row >> tid) & 1u)) alive = false;
                nsel++;
                am = __ballot_sync(FULL, alive);
            }
            int bse = nsel - __popc(selM);
            if ((selM >> tid) & 1u)
                sOrder[bse + __popc(selM & ((1u << tid) - 1u))] = cb + tid;
            unsigned mm = selM;
            while (mm) {
                int l = __ffs(mm) - 1; mm &= mm - 1;
                if (tid < WORDS) sSup[tid] |= sMat[(cb + l) * WORDS + tid];
            }
            __syncwarp();
        }
        if (tid == 0) sNsel = nsel;
    }
    __syncthreads();
    int nsel = sNsel;

    if (tid < nsel) {
        int o = sOrder[tid];
        unsigned long long key = sKeys[o];
        sSelBox[tid]   = sCBox[o];
        sSelScore[tid] = unordf((unsigned)(key >> 32));
        sSelIdx[tid]   = (int)(~(unsigned)(key & 0xffffffffu));
    }
    __syncthreads();

    // ---- exact fallback (overflow / exhausted window only) ----
    if (nsel < MAXDET && (ovf || cutU > LOU + 1u)) {
        unsigned tauOrd = ovf ? 0xFFFFFFFFu : cutU;
        int T = (N + TILE - 1) / TILE;
        for (int t = tid; t < TMAX; t += NMS_T) {
            unsigned long long best = 0ull;
            if (t < T) {
                int bb = t * TILE;
                for (int k = 0; k < TILE; k++) {
                    int ii = bb + k;
                    if (ii >= N) break;
                    unsigned u = ordf(g_scores[ii]);
                    if (u >= tauOrd) continue;     // consumed in phase 1
                    unsigned long long kk =
                        ((unsigned long long)u << 32) | (unsigned)(~ii);
                    if (kk > best) best = kk;
                }
            }
            sTile[t] = best;
        }
        __syncthreads();

        while (nsel < MAXDET) {
            unsigned long long best = 0ull;
            #pragma unroll
            for (int k = 0; k < TMAX / NMS_T; k++) {
                unsigned long long v = sTile[tid + k * NMS_T];
                best = (v > best) ? v : best;
            }
            #pragma unroll
            for (int off = 16; off; off >>= 1) {
                unsigned long long o = __shfl_down_sync(FULL, best, off);
                best = (o > best) ? o : best;
            }
            if (lane == 0) sWarp[wid] = best;
            __syncthreads();
            if (tid < 32) {
                unsigned long long v = (tid < 16) ? sWarp[tid] : 0ull;
                #pragma unroll
                for (int off = 8; off; off >>= 1) {
                    unsigned long long o = __shfl_down_sync(FULL, v, off);
                    v = (o > v) ? o : v;
                }
                if (tid == 0) sWarp[0] = v;
            }
            __syncthreads();
            unsigned long long win = sWarp[0];
            unsigned hi = (unsigned)(win >> 32);
            if (hi <= 0x007FFFFFu) break;
            int   i   = (int)(~(unsigned)(win & 0xffffffffu));
            float val = unordf(hi);
            if (tid == 0) {
                g_scores[i] = -INFINITY;
                sBx = make_box(((const float4*)anc)[i],
                               ((const float4*)reg)[i], imh, imw);
                sSup1 = 0;
            }
            __syncthreads();
            int t = i / TILE;
            if (tid < TILE) {
                int ii = t * TILE + tid;
                unsigned u = (ii < N) ? ordf(g_scores[ii]) : 0x007FFFFFu;
                unsigned long long kk = 0ull;
                if (u < tauOrd)
                    kk = ((unsigned long long)u << 32) | (unsigned)(~ii);
                #pragma unroll
                for (int off = 16; off; off >>= 1) {
                    unsigned long long o = __shfl_down_sync(FULL, kk, off);
                    kk = (o > kk) ? o : kk;
                }
                if (lane == 0) sTileP[wid] = kk;
            }
            if (tid >= 128 && tid < 128 + nsel) {
                if (iou_gt_half(sSelBox[tid - 128], sBx)) sSup1 = 1;
            }
            __syncthreads();
            if (tid == 0) {
                unsigned long long kk = sTileP[0];
                if (sTileP[1] > kk) kk = sTileP[1];
                if (sTileP[2] > kk) kk = sTileP[2];
                sTile[t] = kk;
                if (!sSup1) {
                    sSelBox[nsel] = sBx; sSelIdx[nsel] = i; sSelScore[nsel] = val;
                    sNsel = nsel + 1;
                }
            }
            __syncthreads();
            nsel = sNsel;
        }
    }
    __syncthreads();
    nsel = sNsel;

    // ---- class argmax for selected rows (warp per row) ----
    for (int r = wid; r < nsel; r += NMS_T / 32) {
        int i = sSelIdx[r];
        const float* row = cls + (long long)i * C;
        float best = -INFINITY;
        int   bidx = 0x7fffffff;
        for (int j = lane; j < C; j += 32) {
            float v = row[j];
            if (v > best) { best = v; bidx = j; }
        }
        #pragma unroll
        for (int off = 16; off; off >>= 1) {
            float ov = __shfl_down_sync(FULL, best, off);
            int   oi = __shfl_down_sync(FULL, bidx, off);
            if (ov > best || (ov == best && oi < bidx)) { best = ov; bidx = oi; }
        }
        if (lane == 0) out[100 + r] = (float)bidx;
    }

    for (int r = tid; r < MAXDET; r += NMS_T) {
        bool k = r < nsel;
        out[r]       = k ? sSelScore[r] : 0.0f;
        out[600 + r] = k ? 1.0f : 0.0f;
        float4 b = k ? sSelBox[r] : make_float4(0.f, 0.f, 0.f, 0.f);
        out[200 + 4 * r + 0] = b.x;
        out[200 + 4 * r + 1] = b.y;
        out[200 + 4 * r + 2] = b.z;
        out[200 + 4 * r + 3] = b.w;
        if (!k) out[100 + r] = -1.0f;
    }
}

extern "C" void kernel_launch(void* const* d_in, const int* in_sizes, int n_in,
                              void* d_out, int out_size) {
    const float* cls = (const float*)d_in[0];
    const float* reg = (const float*)d_in[1];
    const float* anc = (const float*)d_in[2];
    const void*  ph  = d_in[3];
    const void*  pw  = d_in[4];

    int N = in_sizes[2] / 4;
    int C = in_sizes[0] / N;

    if (C == 90) {
        int pairs   = N >> 1;
        int blocksD = (pairs + 63) / 64;   // 64 pairs per 256-thread block
        decode90_kernel<<<blocksD, 256>>>(cls, N);
    } else {
        int blocksD = (N + 7) / 8;
        decodegen_kernel<<<blocksD, 256>>>(cls, N, C);
    }

    nms_kernel<<<1, NMS_T>>>((float*)d_out, cls, reg, anc, ph, pw, N, C);
}

// round 7
// speedup vs baseline: 1.3444x; 1.3444x over previous
#include <cuda_runtime.h>
#include <math.h>

#define N_MAX   196608
#define TILE    96
#define TMAX    2048
#define MAXDET  100
#define MAXC    448           // candidate cap (matrix capacity)
#define WORDS   14            // MAXC / 32
#define SPAN    128u          // window below max, ordered-ulp units
#define LOU     0xBC23D70Au   // ordf(0.01f)
#define NMS_T   512

__device__ float              g_scores[N_MAX];
__device__ unsigned           g_maxu;     // zero-init; reset by nms each replay
__device__ int                g_count;    // reset by nms each replay
__device__ unsigned long long g_candKey[MAXC];

__device__ __forceinline__ unsigned ordf(float f) {
    unsigned u = __float_as_uint(f);
    return (u & 0x80000000u) ? ~u : (u | 0x80000000u);
}
__device__ __forceinline__ float unordf(unsigned u) {
    return __uint_as_float((u & 0x80000000u) ? (u ^ 0x80000000u) : ~u);
}
__device__ __forceinline__ float read_dim(const void* p) {
    int iv = *(const int*)p;
    if (iv >= 1 && iv <= (1 << 20)) return (float)iv;
    float fv = *(const float*)p;
    if (fv >= 1.0f && fv <= 1048576.0f) return fv;
    double dv = *(const double*)p;
    if (dv >= 1.0 && dv <= 1048576.0) return (float)dv;
    long long lv = *(const long long*)p;
    return (float)lv;
}
__device__ __forceinline__ bool iou_gt_half(float4 A, float4 B) {
    float x1 = fmaxf(A.x, B.x), y1 = fmaxf(A.y, B.y);
    float x2 = fminf(A.z, B.z), y2 = fminf(A.w, B.w);
    float inter = fmaxf(x2 - x1, 0.0f) * fmaxf(y2 - y1, 0.0f);
    float a1 = (A.z - A.x) * (A.w - A.y);
    float a2 = (B.z - B.x) * (B.w - B.y);
    float iou = inter / (a1 + a2 - inter + 1e-8f);
    return iou > 0.5f;
}
__device__ __forceinline__ float4 make_box(float4 a, float4 r,
                                           float imh, float imw) {
    float wa  = a.z - a.x;
    float ha  = a.w - a.y;
    float cxa = a.x + 0.5f * wa;
    float cya = a.y + 0.5f * ha;
    float cx  = cxa + r.x * 0.1f * wa;
    float cy  = cya + r.y * 0.1f * ha;
    float w   = expf(r.z * 0.2f) * wa;
    float h   = expf(r.w * 0.2f) * ha;
    float4 b;
    b.x = fminf(fmaxf(cx - 0.5f * w, 0.0f), imw);
    b.y = fminf(fmaxf(cy - 0.5f * h, 0.0f), imh);
    b.z = fminf(fmaxf(cx + 0.5f * w, 0.0f), imw);
    b.w = fminf(fmaxf(cy + 0.5f * h, 0.0f), imh);
    return b;
}

// ---------------------------------------------------------------------------
// Kernel 1 (C==90): 8 threads per anchor-pair, 2 pairs per group; register
// max + 3 shuffles; writes scores only. Zero smem atomics.
// ---------------------------------------------------------------------------
__global__ void decode90_kernel(const float* __restrict__ cls, int N) {
    const unsigned FULL = 0xffffffffu;
    int tid = threadIdx.x;
    int sub = tid & 7;
    int grp = tid >> 3;
    long long P0 = ((long long)blockIdx.x * 32 + grp) * 2;
    int pairs = N >> 1;

    unsigned mA0 = 0u, mB0 = 0u, mA1 = 0u, mB1 = 0u;
    #pragma unroll
    for (int pp = 0; pp < 2; pp++) {
        long long P = P0 + pp;
        unsigned* pA = pp ? &mA1 : &mA0;
        unsigned* pB = pp ? &mB1 : &mB0;
        if (P < pairs) {
            const float4* src = (const float4*)cls + P * 45;
            #pragma unroll
            for (int it = 0; it < 6; it++) {
                int q = sub + it * 8;
                if (q < 45) {
                    float4 v = src[q];
                    if (q < 22) {
                        *pA = max(*pA, ordf(fmaxf(fmaxf(v.x, v.y), fmaxf(v.z, v.w))));
                    } else if (q == 22) {
                        *pA = max(*pA, ordf(fmaxf(v.x, v.y)));
                        *pB = max(*pB, ordf(fmaxf(v.z, v.w)));
                    } else {
                        *pB = max(*pB, ordf(fmaxf(fmaxf(v.x, v.y), fmaxf(v.z, v.w))));
                    }
                }
            }
        }
    }
    #pragma unroll
    for (int off = 1; off <= 4; off <<= 1) {
        mA0 = max(mA0, __shfl_xor_sync(FULL, mA0, off));
        mB0 = max(mB0, __shfl_xor_sync(FULL, mB0, off));
        mA1 = max(mA1, __shfl_xor_sync(FULL, mA1, off));
        mB1 = max(mB1, __shfl_xor_sync(FULL, mB1, off));
    }
    if (P0 < pairs && sub < 2) {
        unsigned u = sub ? mB0 : mA0;
        float best = unordf(u);
        g_scores[2 * P0 + sub] = (best > 0.01f) ? best : -INFINITY;
    }
    if (P0 + 1 < pairs && sub < 2) {
        unsigned u = sub ? mB1 : mA1;
        float best = unordf(u);
        g_scores[2 * (P0 + 1) + sub] = (best > 0.01f) ? best : -INFINITY;
    }
    if ((N & 1) && blockIdx.x == 0 && tid == 0) {
        const float* row = cls + (long long)(N - 1) * 90;
        unsigned u = 0u;
        for (int j = 0; j < 90; j++) u = max(u, ordf(row[j]));
        float best = unordf(u);
        g_scores[N - 1] = (best > 0.01f) ? best : -INFINITY;
        atomicMax(&g_maxu, u);
    }
    unsigned wm = max(max(mA0, mB0), max(mA1, mB1));
    wm = max(wm, __shfl_xor_sync(FULL, wm, 8));
    wm = max(wm, __shfl_xor_sync(FULL, wm, 16));
    if ((tid & 31) == 0) atomicMax(&g_maxu, wm);
}

// Generic-C path: warp per anchor.
__global__ void decodegen_kernel(const float* __restrict__ cls, int N, int C) {
    const unsigned FULL = 0xffffffffu;
    int warp = (blockIdx.x * blockDim.x + threadIdx.x) >> 5;
    int lane = threadIdx.x & 31;
    if (warp >= N) return;
    const float* row = cls + (long long)warp * C;
    unsigned u = 0u;
    for (int j = lane; j < C; j += 32) u = max(u, ordf(row[j]));
    #pragma unroll
    for (int off = 16; off; off >>= 1)
        u = max(u, __shfl_xor_sync(FULL, u, off));
    if (lane == 0) {
        float best = unordf(u);
        g_scores[warp] = (best > 0.01f) ? best : -INFINITY;
        atomicMax(&g_maxu, u);
    }
}

// ---------------------------------------------------------------------------
// Kernel 2: grid-wide compact of window candidates (measured ~5us in R4).
// ---------------------------------------------------------------------------
__global__ void compact_kernel(int N) {
    int gid = blockIdx.x * blockDim.x + threadIdx.x;
    if (gid >= N) return;
    unsigned u = ordf(g_scores[gid]);
    unsigned maxu = g_maxu;
    unsigned cut = (maxu > LOU + 1u + SPAN) ? (maxu - SPAN) : (LOU + 1u);
    if (u >= cut && u > LOU) {
        int pos = atomicAdd(&g_count, 1);
        if (pos < MAXC)
            g_candKey[pos] = ((unsigned long long)u << 32) | (unsigned)(~gid);
    }
}

// ---------------------------------------------------------------------------
// Kernel 3: single block. Load keys, bitonic sort, lazy box decode, parallel
// suppression bitmatrix, mask-only greedy resolve (exact reference order),
// class argmax, output. Exact fallback for adversarial inputs.
// ---------------------------------------------------------------------------
__global__ void nms_kernel(float* __restrict__ out,
                           const float* __restrict__ cls,
                           const float* __restrict__ reg,
                           const float* __restrict__ anc,
                           const void* ph, const void* pw,
                           int N, int C) {
    __shared__ __align__(16) unsigned char sBuf[4096 + MAXC * 16 + MAXC * WORDS * 4];
    unsigned long long* sKeys = (unsigned long long*)sBuf;
    float4*   sCBox = (float4*)(sBuf + 4096);
    unsigned* sMat  = (unsigned*)(sBuf + 4096 + MAXC * 16);
    unsigned long long* sTile = (unsigned long long*)sBuf;   // fallback reuse

    __shared__ unsigned sSup[WORDS];
    __shared__ int    sOrder[MAXDET];
    __shared__ float4 sSelBox[MAXDET];
    __shared__ int    sSelIdx[MAXDET];
    __shared__ float  sSelScore[MAXDET];
    __shared__ int    sNsel, sSup1, sTotal;
    __shared__ unsigned sMaxu;
    __shared__ float4 sBx;
    __shared__ unsigned long long sWarp[16];
    __shared__ unsigned long long sTileP[3];

    int tid  = threadIdx.x;
    int wid  = tid >> 5;
    int lane = tid & 31;
    const unsigned FULL = 0xffffffffu;

    float imw = read_dim(pw);
    float imh = read_dim(ph);

    if (tid == 0) {
        sNsel  = 0;
        sTotal = g_count;
        sMaxu  = g_maxu;
        g_count = 0;          // reset for next graph replay
        g_maxu  = 0u;
    }
    if (tid < WORDS) sSup[tid] = 0u;
    __syncthreads();

    unsigned maxu = sMaxu;
    unsigned cutU = (maxu > LOU + 1u + SPAN) ? (maxu - SPAN) : (LOU + 1u);
    bool ovf = sTotal > MAXC;
    int  cnt = ovf ? 0 : sTotal;

    // ---- load + pad keys, bitonic sort (descending) ----
    int M = 2; while (M < cnt) M <<= 1;
    for (int k = tid; k < M; k += NMS_T)
        sKeys[k] = (k < cnt) ? g_candKey[k] : 0ull;
    __syncthreads();
    if (cnt > 1) {
        for (int k2 = 2; k2 <= M; k2 <<= 1) {
            for (int j = k2 >> 1; j > 0; j >>= 1) {
                for (int i = tid; i < M; i += NMS_T) {
                    int l = i ^ j;
                    if (l > i) {
                        unsigned long long a = sKeys[i], b = sKeys[l];
                        bool desc = ((i & k2) == 0);
                        if (desc ? (a < b) : (a > b)) { sKeys[i] = b; sKeys[l] = a; }
                    }
                }
                __syncthreads();
            }
        }
    }

    // ---- lazy decode candidate boxes ----
    if (tid < cnt) {
        unsigned long long key = sKeys[tid];
        int idx = (int)(~(unsigned)(key & 0xffffffffu));
        sCBox[tid] = make_box(((const float4*)anc)[idx],
                              ((const float4*)reg)[idx], imh, imw);
    }
    __syncthreads();

    // ---- parallel suppression bitmatrix ----
    int nW = (cnt + 31) >> 5;
    for (int r = tid; r < cnt; r += NMS_T) {
        float4 br = sCBox[r];
        for (int w = 0; w < nW; w++) {
            unsigned mm = 0;
            int base = w << 5;
            int lim  = min(32, cnt - base);
            for (int b = 0; b < lim; b++)
                mm |= ((unsigned)iou_gt_half(br, sCBox[base + b])) << b;
            sMat[r * WORDS + w] = mm;
        }
    }
    __syncthreads();

    // ---- greedy resolve in sorted order (warp 0, mask-only) ----
    if (tid < 32) {
        int nsel = 0;
        for (int cb = 0; cb < cnt && nsel < MAXDET; cb += 32) {
            int cw = cb >> 5;
            bool valid = (cb + tid) < cnt;
            unsigned supW = sSup[cw];
            bool alive = valid && !((supW >> tid) & 1u);
            unsigned am = __ballot_sync(FULL, alive);
            unsigned selM = 0;
            while (am && nsel < MAXDET) {
                int l = __ffs(am) - 1;
                selM |= 1u << l;
                unsigned row = sMat[(cb + l) * WORDS + cw];
                if (tid == l) alive = false;
                else if (tid > l && ((row >> tid) & 1u)) alive = false;
                nsel++;
                am = __ballot_sync(FULL, alive);
            }
            int bse = nsel - __popc(selM);
            if ((selM >> tid) & 1u)
                sOrder[bse + __popc(selM & ((1u << tid) - 1u))] = cb + tid;
            unsigned mm = selM;
            while (mm) {
                int l = __ffs(mm) - 1; mm &= mm - 1;
                if (tid < WORDS) sSup[tid] |= sMat[(cb + l) * WORDS + tid];
            }
            __syncwarp();
        }
        if (tid == 0) sNsel = nsel;
    }
    __syncthreads();
    int nsel = sNsel;

    if (tid < nsel) {
        int o = sOrder[tid];
        unsigned long long key = sKeys[o];
        sSelBox[tid]   = sCBox[o];
        sSelScore[tid] = unordf((unsigned)(key >> 32));
        sSelIdx[tid]   = (int)(~(unsigned)(key & 0xffffffffu));
    }
    __syncthreads();

    // ---- exact fallback (overflow / exhausted window only) ----
    if (nsel < MAXDET && (ovf || cutU > LOU + 1u)) {
        unsigned tauOrd = ovf ? 0xFFFFFFFFu : cutU;
        int T = (N + TILE - 1) / TILE;
        for (int t = tid; t < TMAX; t += NMS_T) {
            unsigned long long best = 0ull;
            if (t < T) {
                int bb = t * TILE;
                for (int k = 0; k < TILE; k++) {
                    int ii = bb + k;
                    if (ii >= N) break;
                    unsigned u = ordf(g_scores[ii]);
                    if (u >= tauOrd) continue;     // consumed in phase 1
                    unsigned long long kk =
                        ((unsigned long long)u << 32) | (unsigned)(~ii);
                    if (kk > best) best = kk;
                }
            }
            sTile[t] = best;
        }
        __syncthreads();

        while (nsel < MAXDET) {
            unsigned long long best = 0ull;
            #pragma unroll
            for (int k = 0; k < TMAX / NMS_T; k++) {
                unsigned long long v = sTile[tid + k * NMS_T];
                best = (v > best) ? v : best;
            }
            #pragma unroll
            for (int off = 16; off; off >>= 1) {
                unsigned long long o = __shfl_down_sync(FULL, best, off);
                best = (o > best) ? o : best;
            }
            if (lane == 0) sWarp[wid] = best;
            __syncthreads();
            if (tid < 32) {
                unsigned long long v = (tid < 16) ? sWarp[tid] : 0ull;
                #pragma unroll
                for (int off = 8; off; off >>= 1) {
                    unsigned long long o = __shfl_down_sync(FULL, v, off);
                    v = (o > v) ? o : v;
                }
                if (tid == 0) sWarp[0] = v;
            }
            __syncthreads();
            unsigned long long win = sWarp[0];
            unsigned hi = (unsigned)(win >> 32);
            if (hi <= 0x007FFFFFu) break;
            int   i   = (int)(~(unsigned)(win & 0xffffffffu));
            float val = unordf(hi);
            if (tid == 0) {
                g_scores[i] = -INFINITY;
                sBx = make_box(((const float4*)anc)[i],
                               ((const float4*)reg)[i], imh, imw);
                sSup1 = 0;
            }
            __syncthreads();
            int t = i / TILE;
            if (tid < TILE) {
                int ii = t * TILE + tid;
                unsigned u = (ii < N) ? ordf(g_scores[ii]) : 0x007FFFFFu;
                unsigned long long kk = 0ull;
                if (u < tauOrd)
                    kk = ((unsigned long long)u << 32) | (unsigned)(~ii);
                #pragma unroll
                for (int off = 16; off; off >>= 1) {
                    unsigned long long o = __shfl_down_sync(FULL, kk, off);
                    kk = (o > kk) ? o : kk;
                }
                if (lane == 0) sTileP[wid] = kk;
            }
            if (tid >= 128 && tid < 128 + nsel) {
                if (iou_gt_half(sSelBox[tid - 128], sBx)) sSup1 = 1;
            }
            __syncthreads();
            if (tid == 0) {
                unsigned long long kk = sTileP[0];
                if (sTileP[1] > kk) kk = sTileP[1];
                if (sTileP[2] > kk) kk = sTileP[2];
                sTile[t] = kk;
                if (!sSup1) {
                    sSelBox[nsel] = sBx; sSelIdx[nsel] = i; sSelScore[nsel] = val;
                    sNsel = nsel + 1;
                }
            }
            __syncthreads();
            nsel = sNsel;
        }
    }
    __syncthreads();
    nsel = sNsel;

    // ---- class argmax for selected rows (warp per row) ----
    for (int r = wid; r < nsel; r += NMS_T / 32) {
        int i = sSelIdx[r];
        const float* row = cls + (long long)i * C;
        float best = -INFINITY;
        int   bidx = 0x7fffffff;
        for (int j = lane; j < C; j += 32) {
            float v = row[j];
            if (v > best) { best = v; bidx = j; }
        }
        #pragma unroll
        for (int off = 16; off; off >>= 1) {
            float ov = __shfl_down_sync(FULL, best, off);
            int   oi = __shfl_down_sync(FULL, bidx, off);
            if (ov > best || (ov == best && oi < bidx)) { best = ov; bidx = oi; }
        }
        if (lane == 0) out[100 + r] = (float)bidx;
    }

    for (int r = tid; r < MAXDET; r += NMS_T) {
        bool k = r < nsel;
        out[r]       = k ? sSelScore[r] : 0.0f;
        out[600 + r] = k ? 1.0f : 0.0f;
        float4 b = k ? sSelBox[r] : make_float4(0.f, 0.f, 0.f, 0.f);
        out[200 + 4 * r + 0] = b.x;
        out[200 + 4 * r + 1] = b.y;
        out[200 + 4 * r + 2] = b.z;
        out[200 + 4 * r + 3] = b.w;
        if (!k) out[100 + r] = -1.0f;
    }
}

extern "C" void kernel_launch(void* const* d_in, const int* in_sizes, int n_in,
                              void* d_out, int out_size) {
    const float* cls = (const float*)d_in[0];
    const float* reg = (const float*)d_in[1];
    const float* anc = (const float*)d_in[2];
    const void*  ph  = d_in[3];
    const void*  pw  = d_in[4];

    int N = in_sizes[2] / 4;
    int C = in_sizes[0] / N;

    if (C == 90) {
        int pairs   = N >> 1;
        int blocksD = (pairs + 63) / 64;   // 64 pairs per 256-thread block
        decode90_kernel<<<blocksD, 256>>>(cls, N);
    } else {
        int blocksD = (N + 7) / 8;
        decodegen_kernel<<<blocksD, 256>>>(cls, N, C);
    }

    int blocksC = (N + 255) / 256;
    compact_kernel<<<blocksC, 256>>>(N);

    nms_kernel<<<1, NMS_T>>>((float*)d_out, cls, reg, anc, ph, pw, N, C);
}

// round 8
// speedup vs baseline: 1.4847x; 1.1043x over previous
#include <cuda_runtime.h>
#include <math.h>

#define N_MAX   196608
#define TILE    96
#define TMAX    2048
#define MAXDET  100
#define MAXC    448           // candidate cap (matrix capacity)
#define WORDS   14            // MAXC / 32
#define SPAN    128u          // window below max, ordered-ulp units
#define LOU     0xBC23D70Au   // ordf(0.01f)
#define NMS_T   512

__device__ float              g_scores[N_MAX];
__device__ unsigned           g_maxu;     // zero-init; reset by nms each replay
__device__ int                g_count;    // reset by nms each replay
__device__ unsigned long long g_candKey[MAXC];
__device__ float4             g_candBox[MAXC];

__device__ __forceinline__ unsigned ordf(float f) {
    unsigned u = __float_as_uint(f);
    return (u & 0x80000000u) ? ~u : (u | 0x80000000u);
}
__device__ __forceinline__ float unordf(unsigned u) {
    return __uint_as_float((u & 0x80000000u) ? (u ^ 0x80000000u) : ~u);
}
__device__ __forceinline__ float read_dim(const void* p) {
    int iv = *(const int*)p;
    if (iv >= 1 && iv <= (1 << 20)) return (float)iv;
    float fv = *(const float*)p;
    if (fv >= 1.0f && fv <= 1048576.0f) return fv;
    double dv = *(const double*)p;
    if (dv >= 1.0 && dv <= 1048576.0) return (float)dv;
    long long lv = *(const long long*)p;
    return (float)lv;
}
__device__ __forceinline__ bool iou_gt_half(float4 A, float4 B) {
    float x1 = fmaxf(A.x, B.x), y1 = fmaxf(A.y, B.y);
    float x2 = fminf(A.z, B.z), y2 = fminf(A.w, B.w);
    float inter = fmaxf(x2 - x1, 0.0f) * fmaxf(y2 - y1, 0.0f);
    float a1 = (A.z - A.x) * (A.w - A.y);
    float a2 = (B.z - B.x) * (B.w - B.y);
    float iou = inter / (a1 + a2 - inter + 1e-8f);
    return iou > 0.5f;
}
__device__ __forceinline__ float4 make_box(float4 a, float4 r,
                                           float imh, float imw) {
    float wa  = a.z - a.x;
    float ha  = a.w - a.y;
    float cxa = a.x + 0.5f * wa;
    float cya = a.y + 0.5f * ha;
    float cx  = cxa + r.x * 0.1f * wa;
    float cy  = cya + r.y * 0.1f * ha;
    float w   = expf(r.z * 0.2f) * wa;
    float h   = expf(r.w * 0.2f) * ha;
    float4 b;
    b.x = fminf(fmaxf(cx - 0.5f * w, 0.0f), imw);
    b.y = fminf(fmaxf(cy - 0.5f * h, 0.0f), imh);
    b.z = fminf(fmaxf(cx + 0.5f * w, 0.0f), imw);
    b.w = fminf(fmaxf(cy + 0.5f * h, 0.0f), imh);
    return b;
}

// ---------------------------------------------------------------------------
// Kernel 1 (C==90): 8 threads per anchor-pair, 2 pairs per group; register
// max + 3 shuffles; writes scores only. (Measured 22.1us, 40% DRAM.)
// ---------------------------------------------------------------------------
__global__ void decode90_kernel(const float* __restrict__ cls, int N) {
    const unsigned FULL = 0xffffffffu;
    int tid = threadIdx.x;
    int sub = tid & 7;
    int grp = tid >> 3;
    long long P0 = ((long long)blockIdx.x * 32 + grp) * 2;
    int pairs = N >> 1;

    unsigned mA0 = 0u, mB0 = 0u, mA1 = 0u, mB1 = 0u;
    #pragma unroll
    for (int pp = 0; pp < 2; pp++) {
        long long P = P0 + pp;
        unsigned* pA = pp ? &mA1 : &mA0;
        unsigned* pB = pp ? &mB1 : &mB0;
        if (P < pairs) {
            const float4* src = (const float4*)cls + P * 45;
            #pragma unroll
            for (int it = 0; it < 6; it++) {
                int q = sub + it * 8;
                if (q < 45) {
                    float4 v = src[q];
                    if (q < 22) {
                        *pA = max(*pA, ordf(fmaxf(fmaxf(v.x, v.y), fmaxf(v.z, v.w))));
                    } else if (q == 22) {
                        *pA = max(*pA, ordf(fmaxf(v.x, v.y)));
                        *pB = max(*pB, ordf(fmaxf(v.z, v.w)));
                    } else {
                        *pB = max(*pB, ordf(fmaxf(fmaxf(v.x, v.y), fmaxf(v.z, v.w))));
                    }
                }
            }
        }
    }
    #pragma unroll
    for (int off = 1; off <= 4; off <<= 1) {
        mA0 = max(mA0, __shfl_xor_sync(FULL, mA0, off));
        mB0 = max(mB0, __shfl_xor_sync(FULL, mB0, off));
        mA1 = max(mA1, __shfl_xor_sync(FULL, mA1, off));
        mB1 = max(mB1, __shfl_xor_sync(FULL, mB1, off));
    }
    if (P0 < pairs && sub < 2) {
        unsigned u = sub ? mB0 : mA0;
        float best = unordf(u);
        g_scores[2 * P0 + sub] = (best > 0.01f) ? best : -INFINITY;
    }
    if (P0 + 1 < pairs && sub < 2) {
        unsigned u = sub ? mB1 : mA1;
        float best = unordf(u);
        g_scores[2 * (P0 + 1) + sub] = (best > 0.01f) ? best : -INFINITY;
    }
    if ((N & 1) && blockIdx.x == 0 && tid == 0) {
        const float* row = cls + (long long)(N - 1) * 90;
        unsigned u = 0u;
        for (int j = 0; j < 90; j++) u = max(u, ordf(row[j]));
        float best = unordf(u);
        g_scores[N - 1] = (best > 0.01f) ? best : -INFINITY;
        atomicMax(&g_maxu, u);
    }
    unsigned wm = max(max(mA0, mB0), max(mA1, mB1));
    wm = max(wm, __shfl_xor_sync(FULL, wm, 8));
    wm = max(wm, __shfl_xor_sync(FULL, wm, 16));
    if ((tid & 31) == 0) atomicMax(&g_maxu, wm);
}

// Generic-C path: warp per anchor.
__global__ void decodegen_kernel(const float* __restrict__ cls, int N, int C) {
    const unsigned FULL = 0xffffffffu;
    int warp = (blockIdx.x * blockDim.x + threadIdx.x) >> 5;
    int lane = threadIdx.x & 31;
    if (warp >= N) return;
    const float* row = cls + (long long)warp * C;
    unsigned u = 0u;
    for (int j = lane; j < C; j += 32) u = max(u, ordf(row[j]));
    #pragma unroll
    for (int off = 16; off; off >>= 1)
        u = max(u, __shfl_xor_sync(FULL, u, off));
    if (lane == 0) {
        float best = unordf(u);
        g_scores[warp] = (best > 0.01f) ? best : -INFINITY;
        atomicMax(&g_maxu, u);
    }
}

// ---------------------------------------------------------------------------
// Kernel 2: grid-wide compact of window candidates + box decode (parallel).
// ---------------------------------------------------------------------------
__global__ void compact_kernel(const float* __restrict__ reg,
                               const float* __restrict__ anc,
                               const void* ph, const void* pw, int N) {
    int gid = blockIdx.x * blockDim.x + threadIdx.x;
    if (gid >= N) return;
    unsigned u = ordf(g_scores[gid]);
    unsigned maxu = g_maxu;
    unsigned cut = (maxu > LOU + 1u + SPAN) ? (maxu - SPAN) : (LOU + 1u);
    if (u >= cut && u > LOU) {
        int pos = atomicAdd(&g_count, 1);
        if (pos < MAXC) {
            g_candKey[pos] = ((unsigned long long)u << 32) | (unsigned)(~gid);
            float imw = read_dim(pw);
            float imh = read_dim(ph);
            g_candBox[pos] = make_box(((const float4*)anc)[gid],
                                      ((const float4*)reg)[gid], imh, imw);
        }
    }
}

// ---------------------------------------------------------------------------
// Kernel 3: single block. O(n^2) parallel rank (replaces bitonic), parallel
// suppression bitmatrix, fast-path chunk resolve (exact greedy order),
// winners class argmax, output. Exact fallback retained.
// ---------------------------------------------------------------------------
__global__ void nms_kernel(float* __restrict__ out,
                           const float* __restrict__ cls,
                           const float* __restrict__ reg,
                           const float* __restrict__ anc,
                           const void* ph, const void* pw,
                           int N, int C) {
    // layout: keyRaw[448] | keySorted[448] | cbox[448] | mat[448*14]
    __shared__ __align__(16) unsigned char sBuf[MAXC * 8 + MAXC * 8 + MAXC * 16 + MAXC * WORDS * 4];
    unsigned long long* sKeyRaw = (unsigned long long*)sBuf;
    unsigned long long* sKey    = (unsigned long long*)(sBuf + MAXC * 8);
    float4*   sCBox = (float4*)(sBuf + MAXC * 16);
    unsigned* sMat  = (unsigned*)(sBuf + MAXC * 32);
    unsigned long long* sTile = (unsigned long long*)sBuf;   // fallback alias

    __shared__ unsigned sSup[WORDS];
    __shared__ int    sOrder[MAXDET];
    __shared__ float4 sSelBox[MAXDET];
    __shared__ int    sSelIdx[MAXDET];
    __shared__ float  sSelScore[MAXDET];
    __shared__ int    sNsel, sSup1, sTotal;
    __shared__ unsigned sMaxu;
    __shared__ float4 sBx;
    __shared__ unsigned long long sWarp[16];
    __shared__ unsigned long long sTileP[3];

    int tid  = threadIdx.x;
    int wid  = tid >> 5;
    int lane = tid & 31;
    const unsigned FULL = 0xffffffffu;

    float imw = read_dim(pw);
    float imh = read_dim(ph);

    if (tid == 0) {
        sNsel  = 0;
        sTotal = g_count;
        sMaxu  = g_maxu;
        g_count = 0;          // reset for next graph replay
        g_maxu  = 0u;
    }
    if (tid < WORDS) sSup[tid] = 0u;
    __syncthreads();

    unsigned maxu = sMaxu;
    unsigned cutU = (maxu > LOU + 1u + SPAN) ? (maxu - SPAN) : (LOU + 1u);
    bool ovf = sTotal > MAXC;
    int  cnt = ovf ? 0 : sTotal;

    // ---- load keys + boxes ----
    unsigned long long myKey = 0ull;
    float4 myBox;
    if (tid < cnt) {
        myKey = g_candKey[tid];
        myBox = g_candBox[tid];
        sKeyRaw[tid] = myKey;
    }
    __syncthreads();

    // ---- O(n^2) parallel rank + scatter (descending) ----
    if (tid < cnt) {
        int rank = 0;
        for (int j = 0; j < cnt; j++)
            rank += (sKeyRaw[j] > myKey);
        sKey[rank]  = myKey;
        sCBox[rank] = myBox;
    }
    __syncthreads();

    // ---- parallel suppression bitmatrix ----
    int nW = (cnt + 31) >> 5;
    for (int r = tid; r < cnt; r += NMS_T) {
        float4 br = sCBox[r];
        for (int w = 0; w < nW; w++) {
            unsigned mm = 0;
            int base = w << 5;
            int lim  = min(32, cnt - base);
            for (int b = 0; b < lim; b++)
                mm |= ((unsigned)iou_gt_half(br, sCBox[base + b])) << b;
            sMat[r * WORDS + w] = mm;
        }
    }
    __syncthreads();

    // ---- greedy resolve in sorted order (warp 0) ----
    if (tid < 32) {
        int nsel = 0;
        for (int cb = 0; cb < cnt && nsel < MAXDET; cb += 32) {
            int cw = cb >> 5;
            bool valid = (cb + tid) < cnt;
            bool alive = valid && !((sSup[cw] >> tid) & 1u);
            unsigned myRow = valid ? sMat[(cb + tid) * WORDS + cw] : 0u;
            unsigned am = __ballot_sync(FULL, alive);
            unsigned conf = myRow & am & ((1u << tid) - 1u);
            bool hasConf = alive && (conf != 0u);

            unsigned selM;
            if (!__any_sync(FULL, hasConf)) {
                // fast path: no conflicts among alive -> select all (capped)
                int room = MAXDET - nsel;
                if (__popc(am) <= room) {
                    selM = am;
                } else {
                    int myrank = __popc(am & ((1u << tid) - 1u));
                    selM = __ballot_sync(FULL, alive && (myrank < room));
                }
                if ((selM >> tid) & 1u)
                    sOrder[nsel + __popc(selM & ((1u << tid) - 1u))] = cb + tid;
                nsel += __popc(selM);
            } else {
                // slow path: serial greedy pops (rare)
                selM = 0;
                while (am && nsel < MAXDET) {
                    int l = __ffs(am) - 1;
                    selM |= 1u << l;
                    unsigned rl = sMat[(cb + l) * WORDS + cw];
                    if (tid == l) alive = false;
                    else if (tid > l && ((rl >> tid) & 1u)) alive = false;
                    nsel++;
                    am = __ballot_sync(FULL, alive);
                }
                int bse = nsel - __popc(selM);
                if ((selM >> tid) & 1u)
                    sOrder[bse + __popc(selM & ((1u << tid) - 1u))] = cb + tid;
            }
            // accumulate suppression from selected rows
            unsigned mm2 = selM;
            while (mm2) {
                int l = __ffs(mm2) - 1; mm2 &= mm2 - 1;
                if (tid < WORDS) sSup[tid] |= sMat[(cb + l) * WORDS + tid];
            }
            __syncwarp();
        }
        if (tid == 0) sNsel = nsel;
    }
    __syncthreads();
    int nsel = sNsel;

    if (tid < nsel) {
        int o = sOrder[tid];
        unsigned long long key = sKey[o];
        sSelBox[tid]   = sCBox[o];
        sSelScore[tid] = unordf((unsigned)(key >> 32));
        sSelIdx[tid]   = (int)(~(unsigned)(key & 0xffffffffu));
    }
    __syncthreads();

    // ---- exact fallback (overflow / exhausted window only) ----
    if (nsel < MAXDET && (ovf || cutU > LOU + 1u)) {
        unsigned tauOrd = ovf ? 0xFFFFFFFFu : cutU;
        int T = (N + TILE - 1) / TILE;
        for (int t = tid; t < TMAX; t += NMS_T) {
            unsigned long long best = 0ull;
            if (t < T) {
                int bb = t * TILE;
                for (int k = 0; k < TILE; k++) {
                    int ii = bb + k;
                    if (ii >= N) break;
                    unsigned u = ordf(g_scores[ii]);
                    if (u >= tauOrd) continue;     // consumed in phase 1
                    unsigned long long kk =
                        ((unsigned long long)u << 32) | (unsigned)(~ii);
                    if (kk > best) best = kk;
                }
            }
            sTile[t] = best;
        }
        __syncthreads();

        while (nsel < MAXDET) {
            unsigned long long best = 0ull;
            #pragma unroll
            for (int k = 0; k < TMAX / NMS_T; k++) {
                unsigned long long v = sTile[tid + k * NMS_T];
                best = (v > best) ? v : best;
            }
            #pragma unroll
            for (int off = 16; off; off >>= 1) {
                unsigned long long o = __shfl_down_sync(FULL, best, off);
                best = (o > best) ? o : best;
            }
            if (lane == 0) sWarp[wid] = best;
            __syncthreads();
            if (tid < 32) {
                unsigned long long v = (tid < 16) ? sWarp[tid] : 0ull;
                #pragma unroll
                for (int off = 8; off; off >>= 1) {
                    unsigned long long o = __shfl_down_sync(FULL, v, off);
                    v = (o > v) ? o : v;
                }
                if (tid == 0) sWarp[0] = v;
            }
            __syncthreads();
            unsigned long long win = sWarp[0];
            unsigned hi = (unsigned)(win >> 32);
            if (hi <= 0x007FFFFFu) break;
            int   i   = (int)(~(unsigned)(win & 0xffffffffu));
            float val = unordf(hi);
            if (tid == 0) {
                g_scores[i] = -INFINITY;
                sBx = make_box(((const float4*)anc)[i],
                               ((const float4*)reg)[i], imh, imw);
                sSup1 = 0;
            }
            __syncthreads();
            int t = i / TILE;
            if (tid < TILE) {
                int ii = t * TILE + tid;
                unsigned u = (ii < N) ? ordf(g_scores[ii]) : 0x007FFFFFu;
                unsigned long long kk = 0ull;
                if (u < tauOrd)
                    kk = ((unsigned long long)u << 32) | (unsigned)(~ii);
                #pragma unroll
                for (int off = 16; off; off >>= 1) {
                    unsigned long long o = __shfl_down_sync(FULL, kk, off);
                    kk = (o > kk) ? o : kk;
                }
                if (lane == 0) sTileP[wid] = kk;
            }
            if (tid >= 128 && tid < 128 + nsel) {
                if (iou_gt_half(sSelBox[tid - 128], sBx)) sSup1 = 1;
            }
            __syncthreads();
            if (tid == 0) {
                unsigned long long kk = sTileP[0];
                if (sTileP[1] > kk) kk = sTileP[1];
                if (sTileP[2] > kk) kk = sTileP[2];
                sTile[t] = kk;
                if (!sSup1) {
                    sSelBox[nsel] = sBx; sSelIdx[nsel] = i; sSelScore[nsel] = val;
                    sNsel = nsel + 1;
                }
            }
            __syncthreads();
            nsel = sNsel;
        }
    }
    __syncthreads();
    nsel = sNsel;

    // ---- class argmax for selected rows (warp per row) ----
    for (int r = wid; r < nsel; r += NMS_T / 32) {
        int i = sSelIdx[r];
        const float* row = cls + (long long)i * C;
        float best = -INFINITY;
        int   bidx = 0x7fffffff;
        for (int j = lane; j < C; j += 32) {
            float v = row[j];
            if (v > best) { best = v; bidx = j; }
        }
        #pragma unroll
        for (int off = 16; off; off >>= 1) {
            float ov = __shfl_down_sync(FULL, best, off);
            int   oi = __shfl_down_sync(FULL, bidx, off);
            if (ov > best || (ov == best && oi < bidx)) { best = ov; bidx = oi; }
        }
        if (lane == 0) out[100 + r] = (float)bidx;
    }

    for (int r = tid; r < MAXDET; r += NMS_T) {
        bool k = r < nsel;
        out[r]       = k ? sSelScore[r] : 0.0f;
        out[600 + r] = k ? 1.0f : 0.0f;
        float4 b = k ? sSelBox[r] : make_float4(0.f, 0.f, 0.f, 0.f);
        out[200 + 4 * r + 0] = b.x;
        out[200 + 4 * r + 1] = b.y;
        out[200 + 4 * r + 2] = b.z;
        out[200 + 4 * r + 3] = b.w;
        if (!k) out[100 + r] = -1.0f;
    }
}

extern "C" void kernel_launch(void* const* d_in, const int* in_sizes, int n_in,
                              void* d_out, int out_size) {
    const float* cls = (const float*)d_in[0];
    const float* reg = (const float*)d_in[1];
    const float* anc = (const float*)d_in[2];
    const void*  ph  = d_in[3];
    const void*  pw  = d_in[4];

    int N = in_sizes[2] / 4;
    int C = in_sizes[0] / N;

    if (C == 90) {
        int pairs   = N >> 1;
        int blocksD = (pairs + 63) / 64;   // 64 pairs per 256-thread block
        decode90_kernel<<<blocksD, 256>>>(cls, N);
    } else {
        int blocksD = (N + 7) / 8;
        decodegen_kernel<<<blocksD, 256>>>(cls, N, C);
    }

    int blocksC = (N + 255) / 256;
    compact_kernel<<<blocksC, 256>>>(reg, anc, ph, pw, N);

    nms_kernel<<<1, NMS_T>>>((float*)d_out, cls, reg, anc, ph, pw, N, C);
}

// round 9
// speedup vs baseline: 1.8649x; 1.2561x over previous
#include <cuda_runtime.h>
#include <math.h>

#define N_MAX   196608
#define TILE    96
#define TMAX    2048
#define MAXDET  100
#define MAXC    448           // candidate cap (matrix capacity)
#define WORDS   14            // MAXC / 32
#define SPAN    128u          // window below max, ordered-ulp units
#define LOU     0xBC23D70Au   // ordf(0.01f)
#define NMS_T   512

__device__ float              g_scores[N_MAX];
__device__ unsigned           g_maxu;     // zero-init; reset by nms each replay
__device__ int                g_count;    // reset by nms each replay
__device__ unsigned long long g_candKey[MAXC];
__device__ float4             g_candBox[MAXC];

__device__ __forceinline__ unsigned ordf(float f) {
    unsigned u = __float_as_uint(f);
    return (u & 0x80000000u) ? ~u : (u | 0x80000000u);
}
__device__ __forceinline__ float unordf(unsigned u) {
    return __uint_as_float((u & 0x80000000u) ? (u ^ 0x80000000u) : ~u);
}
__device__ __forceinline__ float read_dim(const void* p) {
    int iv = *(const int*)p;
    if (iv >= 1 && iv <= (1 << 20)) return (float)iv;
    float fv = *(const float*)p;
    if (fv >= 1.0f && fv <= 1048576.0f) return fv;
    double dv = *(const double*)p;
    if (dv >= 1.0 && dv <= 1048576.0) return (float)dv;
    long long lv = *(const long long*)p;
    return (float)lv;
}
__device__ __forceinline__ bool iou_gt_half(float4 A, float4 B) {
    float x1 = fmaxf(A.x, B.x), y1 = fmaxf(A.y, B.y);
    float x2 = fminf(A.z, B.z), y2 = fminf(A.w, B.w);
    float inter = fmaxf(x2 - x1, 0.0f) * fmaxf(y2 - y1, 0.0f);
    float a1 = (A.z - A.x) * (A.w - A.y);
    float a2 = (B.z - B.x) * (B.w - B.y);
    float iou = inter / (a1 + a2 - inter + 1e-8f);
    return iou > 0.5f;
}
__device__ __forceinline__ float4 make_box(float4 a, float4 r,
                                           float imh, float imw) {
    float wa  = a.z - a.x;
    float ha  = a.w - a.y;
    float cxa = a.x + 0.5f * wa;
    float cya = a.y + 0.5f * ha;
    float cx  = cxa + r.x * 0.1f * wa;
    float cy  = cya + r.y * 0.1f * ha;
    float w   = expf(r.z * 0.2f) * wa;
    float h   = expf(r.w * 0.2f) * ha;
    float4 b;
    b.x = fminf(fmaxf(cx - 0.5f * w, 0.0f), imw);
    b.y = fminf(fmaxf(cy - 0.5f * h, 0.0f), imh);
    b.z = fminf(fmaxf(cx + 0.5f * w, 0.0f), imw);
    b.w = fminf(fmaxf(cy + 0.5f * h, 0.0f), imh);
    return b;
}
__device__ __forceinline__ unsigned ord4max(float4 v) {
    return ordf(fmaxf(fmaxf(v.x, v.y), fmaxf(v.z, v.w)));
}

// ---------------------------------------------------------------------------
// Kernel 1 (C==90): 8 threads per anchor-pair, 2 pairs per group. All 12
// float4 loads hoisted into registers BEFORE reduction (MLP ~12/thread).
// ---------------------------------------------------------------------------
__global__ void __launch_bounds__(256)
decode90_kernel(const float* __restrict__ cls, int N) {
    const unsigned FULL = 0xffffffffu;
    int tid = threadIdx.x;
    int sub = tid & 7;
    int grp = tid >> 3;
    long long P0 = (long long)blockIdx.x * 64 + grp * 2;
    int pairs = N >> 1;
    bool ok0 = P0 < pairs;
    bool ok1 = P0 + 1 < pairs;

    float4 va[6], vb[6];
    {
        long long Pa = ok0 ? P0 : 0;
        long long Pb = ok1 ? (P0 + 1) : Pa;
        const float4* s0 = (const float4*)cls + Pa * 45;
        const float4* s1 = (const float4*)cls + Pb * 45;
        #pragma unroll
        for (int it = 0; it < 6; it++) {
            int q  = sub + it * 8;
            int qc = (q < 45) ? q : 0;       // clamp; masked out below
            va[it] = s0[qc];
            vb[it] = s1[qc];
        }
    }

    unsigned mA0 = 0u, mB0 = 0u, mA1 = 0u, mB1 = 0u;
    #pragma unroll
    for (int it = 0; it < 6; it++) {
        int q = sub + it * 8;
        if (q < 45) {
            float4 x = va[it];
            float4 y = vb[it];
            if (q < 22) {
                mA0 = max(mA0, ord4max(x));
                mA1 = max(mA1, ord4max(y));
            } else if (q == 22) {   // floats 88..91: x,y -> A; z,w -> B
                mA0 = max(mA0, ordf(fmaxf(x.x, x.y)));
                mB0 = max(mB0, ordf(fmaxf(x.z, x.w)));
                mA1 = max(mA1, ordf(fmaxf(y.x, y.y)));
                mB1 = max(mB1, ordf(fmaxf(y.z, y.w)));
            } else {
                mB0 = max(mB0, ord4max(x));
                mB1 = max(mB1, ord4max(y));
            }
        }
    }
    if (!ok0) { mA0 = mB0 = 0u; }
    if (!ok1) { mA1 = mB1 = 0u; }

    #pragma unroll
    for (int off = 1; off <= 4; off <<= 1) {
        mA0 = max(mA0, __shfl_xor_sync(FULL, mA0, off));
        mB0 = max(mB0, __shfl_xor_sync(FULL, mB0, off));
        mA1 = max(mA1, __shfl_xor_sync(FULL, mA1, off));
        mB1 = max(mB1, __shfl_xor_sync(FULL, mB1, off));
    }
    if (ok0 && sub < 2) {
        unsigned u = sub ? mB0 : mA0;
        float best = unordf(u);
        g_scores[2 * P0 + sub] = (best > 0.01f) ? best : -INFINITY;
    }
    if (ok1 && sub < 2) {
        unsigned u = sub ? mB1 : mA1;
        float best = unordf(u);
        g_scores[2 * (P0 + 1) + sub] = (best > 0.01f) ? best : -INFINITY;
    }
    if ((N & 1) && blockIdx.x == 0 && tid == 0) {
        const float* row = cls + (long long)(N - 1) * 90;
        unsigned u = 0u;
        for (int j = 0; j < 90; j++) u = max(u, ordf(row[j]));
        float best = unordf(u);
        g_scores[N - 1] = (best > 0.01f) ? best : -INFINITY;
        atomicMax(&g_maxu, u);
    }
    unsigned wm = max(max(mA0, mB0), max(mA1, mB1));
    wm = max(wm, __shfl_xor_sync(FULL, wm, 8));
    wm = max(wm, __shfl_xor_sync(FULL, wm, 16));
    if ((tid & 31) == 0) atomicMax(&g_maxu, wm);
}

// Generic-C path: warp per anchor.
__global__ void decodegen_kernel(const float* __restrict__ cls, int N, int C) {
    const unsigned FULL = 0xffffffffu;
    int warp = (blockIdx.x * blockDim.x + threadIdx.x) >> 5;
    int lane = threadIdx.x & 31;
    if (warp >= N) return;
    const float* row = cls + (long long)warp * C;
    unsigned u = 0u;
    for (int j = lane; j < C; j += 32) u = max(u, ordf(row[j]));
    #pragma unroll
    for (int off = 16; off; off >>= 1)
        u = max(u, __shfl_xor_sync(FULL, u, off));
    if (lane == 0) {
        float best = unordf(u);
        g_scores[warp] = (best > 0.01f) ? best : -INFINITY;
        atomicMax(&g_maxu, u);
    }
}

// ---------------------------------------------------------------------------
// Kernel 2: grid-wide compact of window candidates + box decode (parallel).
// ---------------------------------------------------------------------------
__global__ void compact_kernel(const float* __restrict__ reg,
                               const float* __restrict__ anc,
                               const void* ph, const void* pw, int N) {
    int gid = blockIdx.x * blockDim.x + threadIdx.x;
    if (gid >= N) return;
    unsigned u = ordf(g_scores[gid]);
    unsigned maxu = g_maxu;
    unsigned cut = (maxu > LOU + 1u + SPAN) ? (maxu - SPAN) : (LOU + 1u);
    if (u >= cut && u > LOU) {
        int pos = atomicAdd(&g_count, 1);
        if (pos < MAXC) {
            g_candKey[pos] = ((unsigned long long)u << 32) | (unsigned)(~gid);
            float imw = read_dim(pw);
            float imh = read_dim(ph);
            g_candBox[pos] = make_box(((const float4*)anc)[gid],
                                      ((const float4*)reg)[gid], imh, imw);
        }
    }
}

// ---------------------------------------------------------------------------
// Kernel 3: single block. O(n^2) parallel rank, (row,word)-parallel
// suppression bitmatrix, fast-path chunk resolve (exact greedy order),
// winners class argmax, output. Exact fallback retained.
// ---------------------------------------------------------------------------
__global__ void nms_kernel(float* __restrict__ out,
                           const float* __restrict__ cls,
                           const float* __restrict__ reg,
                           const float* __restrict__ anc,
                           const void* ph, const void* pw,
                           int N, int C) {
    __shared__ __align__(16) unsigned char sBuf[MAXC * 8 + MAXC * 8 + MAXC * 16 + MAXC * WORDS * 4];
    unsigned long long* sKeyRaw = (unsigned long long*)sBuf;
    unsigned long long* sKey    = (unsigned long long*)(sBuf + MAXC * 8);
    float4*   sCBox = (float4*)(sBuf + MAXC * 16);
    unsigned* sMat  = (unsigned*)(sBuf + MAXC * 32);
    unsigned long long* sTile = (unsigned long long*)sBuf;   // fallback alias

    __shared__ unsigned sSup[WORDS];
    __shared__ int    sOrder[MAXDET];
    __shared__ float4 sSelBox[MAXDET];
    __shared__ int    sSelIdx[MAXDET];
    __shared__ float  sSelScore[MAXDET];
    __shared__ int    sNsel, sSup1, sTotal;
    __shared__ unsigned sMaxu;
    __shared__ float4 sBx;
    __shared__ unsigned long long sWarp[16];
    __shared__ unsigned long long sTileP[3];

    int tid  = threadIdx.x;
    int wid  = tid >> 5;
    int lane = tid & 31;
    const unsigned FULL = 0xffffffffu;

    float imw = read_dim(pw);
    float imh = read_dim(ph);

    if (tid == 0) {
        sNsel  = 0;
        sTotal = g_count;
        sMaxu  = g_maxu;
        g_count = 0;          // reset for next graph replay
        g_maxu  = 0u;
    }
    if (tid < WORDS) sSup[tid] = 0u;
    __syncthreads();

    unsigned maxu = sMaxu;
    unsigned cutU = (maxu > LOU + 1u + SPAN) ? (maxu - SPAN) : (LOU + 1u);
    bool ovf = sTotal > MAXC;
    int  cnt = ovf ? 0 : sTotal;

    // ---- load keys + boxes ----
    unsigned long long myKey = 0ull;
    float4 myBox;
    if (tid < cnt) {
        myKey = g_candKey[tid];
        myBox = g_candBox[tid];
        sKeyRaw[tid] = myKey;
    }
    __syncthreads();

    // ---- O(n^2) parallel rank + scatter (descending) ----
    if (tid < cnt) {
        int rank = 0;
        for (int j = 0; j < cnt; j++)
            rank += (sKeyRaw[j] > myKey);
        sKey[rank]  = myKey;
        sCBox[rank] = myBox;
    }
    __syncthreads();

    // ---- suppression bitmatrix, parallel over (row, word) tasks ----
    int nW = (cnt + 31) >> 5;
    int tasks = cnt * nW;
    for (int t = tid; t < tasks; t += NMS_T) {
        int r = t / nW;
        int w = t - r * nW;
        float4 br = sCBox[r];
        unsigned mm = 0;
        int base = w << 5;
        int lim  = min(32, cnt - base);
        for (int b = 0; b < lim; b++)
            mm |= ((unsigned)iou_gt_half(br, sCBox[base + b])) << b;
        sMat[r * WORDS + w] = mm;
    }
    __syncthreads();

    // ---- greedy resolve in sorted order (warp 0) ----
    if (tid < 32) {
        int nsel = 0;
        for (int cb = 0; cb < cnt && nsel < MAXDET; cb += 32) {
            int cw = cb >> 5;
            bool valid = (cb + tid) < cnt;
            bool alive = valid && !((sSup[cw] >> tid) & 1u);
            unsigned myRow = valid ? sMat[(cb + tid) * WORDS + cw] : 0u;
            unsigned am = __ballot_sync(FULL, alive);
            unsigned conf = myRow & am & ((1u << tid) - 1u);
            bool hasConf = alive && (conf != 0u);

            unsigned selM;
            if (!__any_sync(FULL, hasConf)) {
                int room = MAXDET - nsel;
                if (__popc(am) <= room) {
                    selM = am;
                } else {
                    int myrank = __popc(am & ((1u << tid) - 1u));
                    selM = __ballot_sync(FULL, alive && (myrank < room));
                }
                if ((selM >> tid) & 1u)
                    sOrder[nsel + __popc(selM & ((1u << tid) - 1u))] = cb + tid;
                nsel += __popc(selM);
            } else {
                selM = 0;
                while (am && nsel < MAXDET) {
                    int l = __ffs(am) - 1;
                    selM |= 1u << l;
                    unsigned rl = sMat[(cb + l) * WORDS + cw];
                    if (tid == l) alive = false;
                    else if (tid > l && ((rl >> tid) & 1u)) alive = false;
                    nsel++;
                    am = __ballot_sync(FULL, alive);
                }
                int bse = nsel - __popc(selM);
                if ((selM >> tid) & 1u)
                    sOrder[bse + __popc(selM & ((1u << tid) - 1u))] = cb + tid;
            }
            unsigned mm2 = selM;
            while (mm2) {
                int l = __ffs(mm2) - 1; mm2 &= mm2 - 1;
                if (tid < WORDS) sSup[tid] |= sMat[(cb + l) * WORDS + tid];
            }
            __syncwarp();
        }
        if (tid == 0) sNsel = nsel;
    }
    __syncthreads();
    int nsel = sNsel;

    if (tid < nsel) {
        int o = sOrder[tid];
        unsigned long long key = sKey[o];
        sSelBox[tid]   = sCBox[o];
        sSelScore[tid] = unordf((unsigned)(key >> 32));
        sSelIdx[tid]   = (int)(~(unsigned)(key & 0xffffffffu));
    }
    __syncthreads();

    // ---- exact fallback (overflow / exhausted window only) ----
    if (nsel < MAXDET && (ovf || cutU > LOU + 1u)) {
        unsigned tauOrd = ovf ? 0xFFFFFFFFu : cutU;
        int T = (N + TILE - 1) / TILE;
        for (int t = tid; t < TMAX; t += NMS_T) {
            unsigned long long best = 0ull;
            if (t < T) {
                int bb = t * TILE;
                for (int k = 0; k < TILE; k++) {
                    int ii = bb + k;
                    if (ii >= N) break;
                    unsigned u = ordf(g_scores[ii]);
                    if (u >= tauOrd) continue;     // consumed in phase 1
                    unsigned long long kk =
                        ((unsigned long long)u << 32) | (unsigned)(~ii);
                    if (kk > best) best = kk;
                }
            }
            sTile[t] = best;
        }
        __syncthreads();

        while (nsel < MAXDET) {
            unsigned long long best = 0ull;
            #pragma unroll
            for (int k = 0; k < TMAX / NMS_T; k++) {
                unsigned long long v = sTile[tid + k * NMS_T];
                best = (v > best) ? v : best;
            }
            #pragma unroll
            for (int off = 16; off; off >>= 1) {
                unsigned long long o = __shfl_down_sync(FULL, best, off);
                best = (o > best) ? o : best;
            }
            if (lane == 0) sWarp[wid] = best;
            __syncthreads();
            if (tid < 32) {
                unsigned long long v = (tid < 16) ? sWarp[tid] : 0ull;
                #pragma unroll
                for (int off = 8; off; off >>= 1) {
                    unsigned long long o = __shfl_down_sync(FULL, v, off);
                    v = (o > v) ? o : v;
                }
                if (tid == 0) sWarp[0] = v;
            }
            __syncthreads();
            unsigned long long win = sWarp[0];
            unsigned hi = (unsigned)(win >> 32);
            if (hi <= 0x007FFFFFu) break;
            int   i   = (int)(~(unsigned)(win & 0xffffffffu));
            float val = unordf(hi);
            if (tid == 0) {
                g_scores[i] = -INFINITY;
                sBx = make_box(((const float4*)anc)[i],
                               ((const float4*)reg)[i], imh, imw);
                sSup1 = 0;
            }
            __syncthreads();
            int t = i / TILE;
            if (tid < TILE) {
                int ii = t * TILE + tid;
                unsigned u = (ii < N) ? ordf(g_scores[ii]) : 0x007FFFFFu;
                unsigned long long kk = 0ull;
                if (u < tauOrd)
                    kk = ((unsigned long long)u << 32) | (unsigned)(~ii);
                #pragma unroll
                for (int off = 16; off; off >>= 1) {
                    unsigned long long o = __shfl_down_sync(FULL, kk, off);
                    kk = (o > kk) ? o : kk;
                }
                if (lane == 0) sTileP[wid] = kk;
            }
            if (tid >= 128 && tid < 128 + nsel) {
                if (iou_gt_half(sSelBox[tid - 128], sBx)) sSup1 = 1;
            }
            __syncthreads();
            if (tid == 0) {
                unsigned long long kk = sTileP[0];
                if (sTileP[1] > kk) kk = sTileP[1];
                if (sTileP[2] > kk) kk = sTileP[2];
                sTile[t] = kk;
                if (!sSup1) {
                    sSelBox[nsel] = sBx; sSelIdx[nsel] = i; sSelScore[nsel] = val;
                    sNsel = nsel + 1;
                }
            }
            __syncthreads();
            nsel = sNsel;
        }
    }
    __syncthreads();
    nsel = sNsel;

    // ---- class argmax for selected rows (warp per row) ----
    for (int r = wid; r < nsel; r += NMS_T / 32) {
        int i = sSelIdx[r];
        const float* row = cls + (long long)i * C;
        float best = -INFINITY;
        int   bidx = 0x7fffffff;
        for (int j = lane; j < C; j += 32) {
            float v = row[j];
            if (v > best) { best = v; bidx = j; }
        }
        #pragma unroll
        for (int off = 16; off; off >>= 1) {
            float ov = __shfl_down_sync(FULL, best, off);
            int   oi = __shfl_down_sync(FULL, bidx, off);
            if (ov > best || (ov == best && oi < bidx)) { best = ov; bidx = oi; }
        }
        if (lane == 0) out[100 + r] = (float)bidx;
    }

    for (int r = tid; r < MAXDET; r += NMS_T) {
        bool k = r < nsel;
        out[r]       = k ? sSelScore[r] : 0.0f;
        out[600 + r] = k ? 1.0f : 0.0f;
        float4 b = k ? sSelBox[r] : make_float4(0.f, 0.f, 0.f, 0.f);
        out[200 + 4 * r + 0] = b.x;
        out[200 + 4 * r + 1] = b.y;
        out[200 + 4 * r + 2] = b.z;
        out[200 + 4 * r + 3] = b.w;
        if (!k) out[100 + r] = -1.0f;
    }
}

extern "C" void kernel_launch(void* const* d_in, const int* in_sizes, int n_in,
                              void* d_out, int out_size) {
    const float* cls = (const float*)d_in[0];
    const float* reg = (const float*)d_in[1];
    const float* anc = (const float*)d_in[2];
    const void*  ph  = d_in[3];
    const void*  pw  = d_in[4];

    int N = in_sizes[2] / 4;
    int C = in_sizes[0] / N;

    if (C == 90) {
        int pairs   = N >> 1;
        int blocksD = (pairs + 63) / 64;   // 64 pairs per 256-thread block
        decode90_kernel<<<blocksD, 256>>>(cls, N);
    } else {
        int blocksD = (N + 7) / 8;
        decodegen_kernel<<<blocksD, 256>>>(cls, N, C);
    }

    int blocksC = (N + 255) / 256;
    compact_kernel<<<blocksC, 256>>>(reg, anc, ph, pw, N);

    nms_kernel<<<1, NMS_T>>>((float*)d_out, cls, reg, anc, ph, pw, N, C);
}